// round 2
// baseline (speedup 1.0000x reference)
#include <cuda_runtime.h>
#include <cstdint>

#define NN 100000
#define EE 3200000
#define D_IN 512
#define D_HID 16
#define N_CLS 7

// Scratch (device globals: allocation-free per harness rules)
__device__ __align__(16) float g_h1[NN * D_HID];     // x @ W1
__device__ __align__(16) float g_agg1[NN * D_HID];   // scatter-add of h1
__device__ __align__(16) float g_h2[NN * 8];         // relu(agg1+b1) @ W2, padded 7->8
__device__ __align__(16) float g_agg2[NN * 8];       // scatter-add of h2, padded
__device__ int g_is64;                               // edge-index dtype flag

__device__ __forceinline__ void red_add_v4(float* addr, float4 v) {
    asm volatile("{ .reg .u64 ga;\n\t"
                 "cvta.to.global.u64 ga, %0;\n\t"
                 "red.global.add.v4.f32 [ga], {%1,%2,%3,%4}; }"
                 :: "l"(addr), "f"(v.x), "f"(v.y), "f"(v.z), "f"(v.w)
                 : "memory");
}

// ---------------------------------------------------------------------------
// Detect edge-index dtype: int64 node-ids (<2^31) have all-zero odd 32b words.
// ---------------------------------------------------------------------------
__global__ void k_detect(const int* __restrict__ ei) {
    if (threadIdx.x == 0 && blockIdx.x == 0) {
        int s = 0;
        #pragma unroll
        for (int i = 1; i < 64; i += 2) s |= ei[i];
        g_is64 = (s == 0) ? 1 : 0;
    }
}

// ---------------------------------------------------------------------------
// Zero the scatter accumulators (must happen every launch: graph replay)
// ---------------------------------------------------------------------------
__global__ void k_init() {
    int i = blockIdx.x * blockDim.x + threadIdx.x;
    float4 z = make_float4(0.f, 0.f, 0.f, 0.f);
    if (i < NN * 4) {                       // agg1: NN*16 floats = NN*4 float4
        reinterpret_cast<float4*>(g_agg1)[i] = z;
    }
    int j = i - NN * 4;
    if (j >= 0 && j < NN * 2) {             // agg2: NN*8 floats = NN*2 float4
        reinterpret_cast<float4*>(g_agg2)[j] = z;
    }
}

// ---------------------------------------------------------------------------
// GEMM1: g_h1 = x @ W1.  One warp per 4 nodes, split-K across 32 lanes.
// x read coalesced straight from global; W1^T staged in smem (padded rows).
// ---------------------------------------------------------------------------
#define WPITCH 513

__device__ __forceinline__ void warp_reduce16_store(float v[16], int lane, float* dst) {
    // Halving-merge butterfly: 16 values x 32 lanes -> each lane-pair owns one j.
    #pragma unroll
    for (int t = 0; t < 8; t++) {
        bool hi = (lane & 16) != 0;
        float keep = hi ? v[t + 8] : v[t];
        float give = hi ? v[t] : v[t + 8];
        v[t] = keep + __shfl_xor_sync(0xffffffffu, give, 16);
    }
    #pragma unroll
    for (int t = 0; t < 4; t++) {
        bool hi = (lane & 8) != 0;
        float keep = hi ? v[t + 4] : v[t];
        float give = hi ? v[t] : v[t + 4];
        v[t] = keep + __shfl_xor_sync(0xffffffffu, give, 8);
    }
    #pragma unroll
    for (int t = 0; t < 2; t++) {
        bool hi = (lane & 4) != 0;
        float keep = hi ? v[t + 2] : v[t];
        float give = hi ? v[t] : v[t + 2];
        v[t] = keep + __shfl_xor_sync(0xffffffffu, give, 4);
    }
    {
        bool hi = (lane & 2) != 0;
        float keep = hi ? v[1] : v[0];
        float give = hi ? v[0] : v[1];
        v[0] = keep + __shfl_xor_sync(0xffffffffu, give, 2);
    }
    v[0] += __shfl_xor_sync(0xffffffffu, v[0], 1);
    // After the masks {16,8,4,2}, lane pair (2p, 2p+1) owns j = (lane>>1)&15.
    if ((lane & 1) == 0) dst[(lane >> 1) & 15] = v[0];
}

__global__ __launch_bounds__(256) void k_gemm1(const float* __restrict__ x,
                                               const float* __restrict__ W1) {
    __shared__ float ws[16 * WPITCH];   // ws[j*WPITCH + k] = W1[k][j]
    int tid = threadIdx.x;
    #pragma unroll
    for (int i = 0; i < 32; i++) {
        int idx = tid + i * 256;        // idx over 512*16
        int k = idx >> 4;
        int j = idx & 15;
        ws[j * WPITCH + k] = W1[idx];
    }
    __syncthreads();

    int warp = tid >> 5, lane = tid & 31;
    int node0 = blockIdx.x * 32 + warp * 4;   // NN = 3125*32 exactly
    const float* xp = x + (size_t)node0 * D_IN + lane;

    float a0[16], a1[16], a2[16], a3[16];
    #pragma unroll
    for (int j = 0; j < 16; j++) { a0[j] = a1[j] = a2[j] = a3[j] = 0.f; }

    #pragma unroll 4
    for (int i = 0; i < 16; i++) {
        float x0 = xp[i * 32];
        float x1 = xp[i * 32 + 512];
        float x2 = xp[i * 32 + 1024];
        float x3 = xp[i * 32 + 1536];
        const float* wk = &ws[i * 32 + lane];
        #pragma unroll
        for (int j = 0; j < 16; j++) {
            float w = wk[j * WPITCH];   // lanes hit consecutive banks: conflict-free
            a0[j] = fmaf(x0, w, a0[j]);
            a1[j] = fmaf(x1, w, a1[j]);
            a2[j] = fmaf(x2, w, a2[j]);
            a3[j] = fmaf(x3, w, a3[j]);
        }
    }

    warp_reduce16_store(a0, lane, g_h1 + (size_t)(node0 + 0) * 16);
    warp_reduce16_store(a1, lane, g_h1 + (size_t)(node0 + 1) * 16);
    warp_reduce16_store(a2, lane, g_h1 + (size_t)(node0 + 2) * 16);
    warp_reduce16_store(a3, lane, g_h1 + (size_t)(node0 + 3) * 16);
}

// ---------------------------------------------------------------------------
// Edge fetch helper: dtype-agnostic (int64 vs int32), bounds-guarded.
// ---------------------------------------------------------------------------
__device__ __forceinline__ bool load_edge(const void* ei, int e, int& src, int& dst) {
    if (g_is64) {
        const long long* p = (const long long*)ei;
        src = (int)p[e];
        dst = (int)p[EE + e];
    } else {
        const int* p = (const int*)ei;
        src = p[e];
        dst = p[EE + e];
    }
    return ((unsigned)src < NN) && ((unsigned)dst < NN);
}

// ---------------------------------------------------------------------------
// Scatter1: agg1[dst] += h1[src] over 3.2M edges (4x v4 atomics per edge)
// ---------------------------------------------------------------------------
__global__ void k_scatter1(const void* __restrict__ ei) {
    int e = blockIdx.x * blockDim.x + threadIdx.x;
    if (e >= EE) return;
    int src, dst;
    if (!load_edge(ei, e, src, dst)) return;
    const float4* hp = reinterpret_cast<const float4*>(g_h1 + (size_t)src * 16);
    float* ap = g_agg1 + (size_t)dst * 16;
    float4 v0 = hp[0], v1 = hp[1], v2 = hp[2], v3 = hp[3];
    red_add_v4(ap + 0, v0);
    red_add_v4(ap + 4, v1);
    red_add_v4(ap + 8, v2);
    red_add_v4(ap + 12, v3);
}

// ---------------------------------------------------------------------------
// GEMM2: g_h2 = relu(agg1 + b1) @ W2  (row padded to 8 floats, last = 0)
// ---------------------------------------------------------------------------
__global__ __launch_bounds__(256) void k_gemm2(const float* __restrict__ b1,
                                               const float* __restrict__ W2) {
    __shared__ float w2s[16 * 7];
    __shared__ float b1s[16];
    if (threadIdx.x < 112) w2s[threadIdx.x] = W2[threadIdx.x];
    if (threadIdx.x < 16)  b1s[threadIdx.x] = b1[threadIdx.x];
    __syncthreads();

    int n = blockIdx.x * blockDim.x + threadIdx.x;
    if (n >= NN) return;

    const float4* ap = reinterpret_cast<const float4*>(g_agg1 + (size_t)n * 16);
    float h[16];
    float4 t0 = ap[0], t1 = ap[1], t2 = ap[2], t3 = ap[3];
    h[0] = t0.x; h[1] = t0.y; h[2]  = t0.z; h[3]  = t0.w;
    h[4] = t1.x; h[5] = t1.y; h[6]  = t1.z; h[7]  = t1.w;
    h[8] = t2.x; h[9] = t2.y; h[10] = t2.z; h[11] = t2.w;
    h[12] = t3.x; h[13] = t3.y; h[14] = t3.z; h[15] = t3.w;
    #pragma unroll
    for (int j = 0; j < 16; j++) h[j] = fmaxf(h[j] + b1s[j], 0.f);

    float o[8];
    #pragma unroll
    for (int c = 0; c < 7; c++) {
        float s = 0.f;
        #pragma unroll
        for (int j = 0; j < 16; j++) s = fmaf(h[j], w2s[j * 7 + c], s);
        o[c] = s;
    }
    o[7] = 0.f;

    float4* op = reinterpret_cast<float4*>(g_h2 + (size_t)n * 8);
    op[0] = make_float4(o[0], o[1], o[2], o[3]);
    op[1] = make_float4(o[4], o[5], o[6], o[7]);
}

// ---------------------------------------------------------------------------
// Scatter2: agg2[dst] += h2[src] (2x v4 atomics per edge, padded rows)
// ---------------------------------------------------------------------------
__global__ void k_scatter2(const void* __restrict__ ei) {
    int e = blockIdx.x * blockDim.x + threadIdx.x;
    if (e >= EE) return;
    int src, dst;
    if (!load_edge(ei, e, src, dst)) return;
    const float4* hp = reinterpret_cast<const float4*>(g_h2 + (size_t)src * 8);
    float* ap = g_agg2 + (size_t)dst * 8;
    float4 v0 = hp[0], v1 = hp[1];
    red_add_v4(ap + 0, v0);
    red_add_v4(ap + 4, v1);
}

// ---------------------------------------------------------------------------
// Epilogue: out[n][c] = agg2[n][c] + b2[c]   (strips the padding)
// ---------------------------------------------------------------------------
__global__ void k_final(const float* __restrict__ b2, float* __restrict__ out) {
    int i = blockIdx.x * blockDim.x + threadIdx.x;
    if (i >= NN * N_CLS) return;
    int n = i / 7;
    int c = i - n * 7;
    out[i] = g_agg2[n * 8 + c] + b2[c];
}

// ---------------------------------------------------------------------------
extern "C" void kernel_launch(void* const* d_in, const int* in_sizes, int n_in,
                              void* d_out, int out_size) {
    // Map inputs by element count (all six are distinct) — immune to ordering.
    const float* x  = nullptr;
    const void*  ei = nullptr;
    const float* W1 = nullptr;
    const float* b1 = nullptr;
    const float* W2 = nullptr;
    const float* b2 = nullptr;
    for (int i = 0; i < n_in; i++) {
        switch (in_sizes[i]) {
            case NN * D_IN:        x  = (const float*)d_in[i]; break;  // 51,200,000
            case 2 * EE:           ei = d_in[i];                break;  // 6,400,000
            case D_IN * D_HID:     W1 = (const float*)d_in[i]; break;  // 8192
            case D_HID:            b1 = (const float*)d_in[i]; break;  // 16
            case D_HID * N_CLS:    W2 = (const float*)d_in[i]; break;  // 112
            case N_CLS:            b2 = (const float*)d_in[i]; break;  // 7
            default: break;
        }
    }
    float* out = (float*)d_out;

    k_detect<<<1, 32>>>((const int*)ei);
    k_init<<<(NN * 4 + NN * 2 + 255) / 256, 256>>>();
    k_gemm1<<<NN / 32, 256>>>(x, W1);
    k_scatter1<<<(EE + 255) / 256, 256>>>(ei);
    k_gemm2<<<(NN + 255) / 256, 256>>>(b1, W2);
    k_scatter2<<<(EE + 255) / 256, 256>>>(ei);
    k_final<<<(NN * N_CLS + 255) / 256, 256>>>(b2, out);
}

// round 3
// speedup vs baseline: 1.4416x; 1.4416x over previous
#include <cuda_runtime.h>
#include <cstdint>

#define NN 100000
#define EE 3200000
#define D_IN 512
#define D_HID 16
#define N_CLS 7

typedef unsigned long long ull;

// Scratch (device globals: allocation-free per harness rules)
__device__ __align__(16) float g_h1[NN * D_HID];     // x @ W1
__device__ __align__(16) float g_agg1[NN * D_HID];   // scatter-add of h1
__device__ __align__(16) float g_h2[NN * 8];         // relu(agg1+b1) @ W2, padded 7->8
__device__ __align__(16) float g_agg2[NN * 8];       // scatter-add of h2, padded
__device__ int g_is64;                               // edge-index dtype flag

__device__ __forceinline__ void red_add_v4(float* addr, float4 v) {
    asm volatile("{ .reg .u64 ga;\n\t"
                 "cvta.to.global.u64 ga, %0;\n\t"
                 "red.global.add.v4.f32 [ga], {%1,%2,%3,%4}; }"
                 :: "l"(addr), "f"(v.x), "f"(v.y), "f"(v.z), "f"(v.w)
                 : "memory");
}

// Packed f32x2 FMA: a += x * w elementwise on two packed floats.
__device__ __forceinline__ void fma2(ull& a, ull x, ull w) {
    asm("fma.rn.f32x2 %0, %1, %2, %0;" : "+l"(a) : "l"(x), "l"(w));
}
__device__ __forceinline__ float fold2(ull a) {
    float lo, hi;
    asm("mov.b64 {%0,%1}, %2;" : "=f"(lo), "=f"(hi) : "l"(a));
    return lo + hi;
}

// ---------------------------------------------------------------------------
// Detect edge-index dtype: int64 node-ids (<2^31) have all-zero odd 32b words.
// ---------------------------------------------------------------------------
__global__ void k_detect(const int* __restrict__ ei) {
    if (threadIdx.x == 0 && blockIdx.x == 0) {
        int s = 0;
        #pragma unroll
        for (int i = 1; i < 64; i += 2) s |= ei[i];
        g_is64 = (s == 0) ? 1 : 0;
    }
}

// ---------------------------------------------------------------------------
// Zero the scatter accumulators (must happen every launch: graph replay)
// ---------------------------------------------------------------------------
__global__ void k_init() {
    int i = blockIdx.x * blockDim.x + threadIdx.x;
    float4 z = make_float4(0.f, 0.f, 0.f, 0.f);
    if (i < NN * 4) {                       // agg1: NN*16 floats = NN*4 float4
        reinterpret_cast<float4*>(g_agg1)[i] = z;
    }
    int j = i - NN * 4;
    if (j >= 0 && j < NN * 2) {             // agg2: NN*8 floats = NN*2 float4
        reinterpret_cast<float4*>(g_agg2)[j] = z;
    }
}

// ---------------------------------------------------------------------------
// GEMM1: g_h1 = x @ W1.  One warp per 4 nodes, split-K across 32 lanes,
// packed f32x2 FMAs (K-pairs). x read coalesced from global (LDG.64/lane);
// W1^T staged in smem, read as 8B packed pairs conflict-free.
// ---------------------------------------------------------------------------
#define WPITCH_F 514          // floats per j-row (even, 2-way-max conflicts on store)
#define WPITCH_U 257          // ull per j-row

__device__ __forceinline__ void warp_reduce16_store(float v[16], int lane, float* dst) {
    // Halving-merge butterfly: 16 values x 32 lanes -> each lane-pair owns one j.
    #pragma unroll
    for (int t = 0; t < 8; t++) {
        bool hi = (lane & 16) != 0;
        float keep = hi ? v[t + 8] : v[t];
        float give = hi ? v[t] : v[t + 8];
        v[t] = keep + __shfl_xor_sync(0xffffffffu, give, 16);
    }
    #pragma unroll
    for (int t = 0; t < 4; t++) {
        bool hi = (lane & 8) != 0;
        float keep = hi ? v[t + 4] : v[t];
        float give = hi ? v[t] : v[t + 4];
        v[t] = keep + __shfl_xor_sync(0xffffffffu, give, 8);
    }
    #pragma unroll
    for (int t = 0; t < 2; t++) {
        bool hi = (lane & 4) != 0;
        float keep = hi ? v[t + 2] : v[t];
        float give = hi ? v[t] : v[t + 2];
        v[t] = keep + __shfl_xor_sync(0xffffffffu, give, 4);
    }
    {
        bool hi = (lane & 2) != 0;
        float keep = hi ? v[1] : v[0];
        float give = hi ? v[0] : v[1];
        v[0] = keep + __shfl_xor_sync(0xffffffffu, give, 2);
    }
    v[0] += __shfl_xor_sync(0xffffffffu, v[0], 1);
    // After the masks {16,8,4,2}, lane pair (2p, 2p+1) owns j = (lane>>1)&15.
    if ((lane & 1) == 0) dst[(lane >> 1) & 15] = v[0];
}

__global__ __launch_bounds__(128) void k_gemm1(const float* __restrict__ x,
                                               const float* __restrict__ W1) {
    __shared__ float wsf[16 * WPITCH_F];   // wsf[j*514 + k] = W1[k][j]
    int tid = threadIdx.x;
    #pragma unroll
    for (int t = 0; t < 64; t++) {
        int idx = tid + t * 128;           // 0..8191, coalesced W1 reads
        int k = idx >> 4;
        int j = idx & 15;
        wsf[j * WPITCH_F + k] = W1[idx];
    }
    __syncthreads();
    const ull* ws2 = reinterpret_cast<const ull*>(wsf);

    int warp = tid >> 5, lane = tid & 31;
    int node0 = blockIdx.x * 16 + warp * 4;        // NN = 6250*16 exactly
    const ull* xp = reinterpret_cast<const ull*>(x + (size_t)node0 * D_IN) + lane;

    ull a0[16], a1[16], a2[16], a3[16];
    #pragma unroll
    for (int j = 0; j < 16; j++) { a0[j] = a1[j] = a2[j] = a3[j] = 0ull; }

    #pragma unroll
    for (int i = 0; i < 8; i++) {
        ull x0 = xp[i * 32];
        ull x1 = xp[i * 32 + 256];
        ull x2 = xp[i * 32 + 512];
        ull x3 = xp[i * 32 + 768];
        const ull* wk = ws2 + i * 32 + lane;
        #pragma unroll
        for (int j = 0; j < 16; j++) {
            ull w = wk[j * WPITCH_U];      // lanes consecutive 8B: conflict-free
            fma2(a0[j], x0, w);
            fma2(a1[j], x1, w);
            fma2(a2[j], x2, w);
            fma2(a3[j], x3, w);
        }
    }

    float v[16];
    #pragma unroll
    for (int j = 0; j < 16; j++) v[j] = fold2(a0[j]);
    warp_reduce16_store(v, lane, g_h1 + (size_t)(node0 + 0) * 16);
    #pragma unroll
    for (int j = 0; j < 16; j++) v[j] = fold2(a1[j]);
    warp_reduce16_store(v, lane, g_h1 + (size_t)(node0 + 1) * 16);
    #pragma unroll
    for (int j = 0; j < 16; j++) v[j] = fold2(a2[j]);
    warp_reduce16_store(v, lane, g_h1 + (size_t)(node0 + 2) * 16);
    #pragma unroll
    for (int j = 0; j < 16; j++) v[j] = fold2(a3[j]);
    warp_reduce16_store(v, lane, g_h1 + (size_t)(node0 + 3) * 16);
}

// ---------------------------------------------------------------------------
// Scatter1: agg1[dst] += h1[src].  4 lanes per edge (one 16B chunk each) so
// gathers of a 64B row coalesce into the same 128B line. 8 edges per warp.
// ---------------------------------------------------------------------------
__global__ __launch_bounds__(256) void k_scatter1(const void* __restrict__ ei) {
    int warpGlobal = (blockIdx.x * 256 + threadIdx.x) >> 5;
    int lane = threadIdx.x & 31;
    int e_base = warpGlobal * 8;                  // EE = 50000*8*8 exactly
    int s = 0, d = 0;
    if (lane < 8) {
        int e = e_base + lane;
        if (g_is64) {
            const long long* p = (const long long*)ei;
            s = (int)p[e];
            d = (int)p[EE + e];
        } else {
            const int* p = (const int*)ei;
            s = p[e];
            d = p[EE + e];
        }
    }
    int eloc = lane >> 2;
    int src = __shfl_sync(0xffffffffu, s, eloc);
    int dst = __shfl_sync(0xffffffffu, d, eloc);
    if ((unsigned)src >= NN || (unsigned)dst >= NN) return;
    int chunk = lane & 3;
    float4 v = reinterpret_cast<const float4*>(g_h1)[src * 4 + chunk];
    red_add_v4(g_agg1 + (size_t)dst * 16 + chunk * 4, v);
}

// ---------------------------------------------------------------------------
// GEMM2: g_h2 = relu(agg1 + b1) @ W2  (row padded to 8 floats, last = 0)
// ---------------------------------------------------------------------------
__global__ __launch_bounds__(256) void k_gemm2(const float* __restrict__ b1,
                                               const float* __restrict__ W2) {
    __shared__ float w2s[16 * 7];
    __shared__ float b1s[16];
    if (threadIdx.x < 112) w2s[threadIdx.x] = W2[threadIdx.x];
    if (threadIdx.x < 16)  b1s[threadIdx.x] = b1[threadIdx.x];
    __syncthreads();

    int n = blockIdx.x * blockDim.x + threadIdx.x;
    if (n >= NN) return;

    const float4* ap = reinterpret_cast<const float4*>(g_agg1 + (size_t)n * 16);
    float h[16];
    float4 t0 = ap[0], t1 = ap[1], t2 = ap[2], t3 = ap[3];
    h[0] = t0.x; h[1] = t0.y; h[2]  = t0.z; h[3]  = t0.w;
    h[4] = t1.x; h[5] = t1.y; h[6]  = t1.z; h[7]  = t1.w;
    h[8] = t2.x; h[9] = t2.y; h[10] = t2.z; h[11] = t2.w;
    h[12] = t3.x; h[13] = t3.y; h[14] = t3.z; h[15] = t3.w;
    #pragma unroll
    for (int j = 0; j < 16; j++) h[j] = fmaxf(h[j] + b1s[j], 0.f);

    float o[8];
    #pragma unroll
    for (int c = 0; c < 7; c++) {
        float s = 0.f;
        #pragma unroll
        for (int j = 0; j < 16; j++) s = fmaf(h[j], w2s[j * 7 + c], s);
        o[c] = s;
    }
    o[7] = 0.f;

    float4* op = reinterpret_cast<float4*>(g_h2 + (size_t)n * 8);
    op[0] = make_float4(o[0], o[1], o[2], o[3]);
    op[1] = make_float4(o[4], o[5], o[6], o[7]);
}

// ---------------------------------------------------------------------------
// Scatter2: agg2[dst] += h2[src].  2 lanes per edge, 16 edges per warp.
// ---------------------------------------------------------------------------
__global__ __launch_bounds__(256) void k_scatter2(const void* __restrict__ ei) {
    int warpGlobal = (blockIdx.x * 256 + threadIdx.x) >> 5;
    int lane = threadIdx.x & 31;
    int e_base = warpGlobal * 16;                 // EE = 25000*8*16 exactly
    int s = 0, d = 0;
    if (lane < 16) {
        int e = e_base + lane;
        if (g_is64) {
            const long long* p = (const long long*)ei;
            s = (int)p[e];
            d = (int)p[EE + e];
        } else {
            const int* p = (const int*)ei;
            s = p[e];
            d = p[EE + e];
        }
    }
    int eloc = lane >> 1;
    int src = __shfl_sync(0xffffffffu, s, eloc);
    int dst = __shfl_sync(0xffffffffu, d, eloc);
    if ((unsigned)src >= NN || (unsigned)dst >= NN) return;
    int chunk = lane & 1;
    float4 v = reinterpret_cast<const float4*>(g_h2)[src * 2 + chunk];
    red_add_v4(g_agg2 + (size_t)dst * 8 + chunk * 4, v);
}

// ---------------------------------------------------------------------------
// Epilogue: out[n][c] = agg2[n][c] + b2[c]   (strips the padding)
// ---------------------------------------------------------------------------
__global__ void k_final(const float* __restrict__ b2, float* __restrict__ out) {
    int i = blockIdx.x * blockDim.x + threadIdx.x;
    if (i >= NN * N_CLS) return;
    int n = i / 7;
    int c = i - n * 7;
    out[i] = g_agg2[n * 8 + c] + b2[c];
}

// ---------------------------------------------------------------------------
extern "C" void kernel_launch(void* const* d_in, const int* in_sizes, int n_in,
                              void* d_out, int out_size) {
    // Map inputs by element count (all six are distinct) — immune to ordering.
    const float* x  = nullptr;
    const void*  ei = nullptr;
    const float* W1 = nullptr;
    const float* b1 = nullptr;
    const float* W2 = nullptr;
    const float* b2 = nullptr;
    for (int i = 0; i < n_in; i++) {
        switch (in_sizes[i]) {
            case NN * D_IN:        x  = (const float*)d_in[i]; break;  // 51,200,000
            case 2 * EE:           ei = d_in[i];                break;  // 6,400,000
            case D_IN * D_HID:     W1 = (const float*)d_in[i]; break;  // 8192
            case D_HID:            b1 = (const float*)d_in[i]; break;  // 16
            case D_HID * N_CLS:    W2 = (const float*)d_in[i]; break;  // 112
            case N_CLS:            b2 = (const float*)d_in[i]; break;  // 7
            default: break;
        }
    }
    float* out = (float*)d_out;

    k_detect<<<1, 32>>>((const int*)ei);
    k_init<<<(NN * 6 + 255) / 256, 256>>>();
    k_gemm1<<<NN / 16, 128>>>(x, W1);
    k_scatter1<<<EE / 64, 256>>>(ei);
    k_gemm2<<<(NN + 255) / 256, 256>>>(b1, W2);
    k_scatter2<<<EE / 128, 256>>>(ei);
    k_final<<<(NN * N_CLS + 255) / 256, 256>>>(b2, out);
}